// round 2
// baseline (speedup 1.0000x reference)
#include <cuda_runtime.h>
#include <cuda_bf16.h>
#include <cstdint>

// Problem constants
#define TOT_ROWS 16384   // B*N = 4*4096
#define DIM      1024
#define BOT      64
// Tiling
#define MTILE    64      // rows per CTA
#define KC       64      // K-chunk for GEMM1
#define NKC      16      // DIM/KC
#define NCH      128     // N-chunk for GEMM2
#define NNC      8       // DIM/NCH
#define NTHR     512
#define SPAD     72      // smem row stride (bf16 elems): 144B = 9*16B, conflict-free

// ---------------- device scratch (no allocations allowed) ----------------
__device__ __nv_bfloat16 g_WdT[BOT * DIM];   // [j][d] = bf16(norm_w[d] * w_down[d][j])
__device__ __nv_bfloat16 g_WuT[DIM * BOT];   // [n][k] = bf16(w_up[k][n])
__device__ float         g_cf[2 * BOT];      // c[64], f[64]

// ---------------- small helpers ----------------
__device__ __forceinline__ void cp16(void* s, const void* g) {
    uint32_t sa = (uint32_t)__cvta_generic_to_shared(s);
    asm volatile("cp.async.cg.shared.global [%0], [%1], 16;\n" :: "r"(sa), "l"(g));
}
__device__ __forceinline__ void cp_commit() { asm volatile("cp.async.commit_group;\n"); }
__device__ __forceinline__ void cp_wait0()  { asm volatile("cp.async.wait_group 0;\n"); }

__device__ __forceinline__ void mma_bf16(float* d, const uint32_t* a, const uint32_t* b) {
    asm volatile(
        "mma.sync.aligned.m16n8k16.row.col.f32.bf16.bf16.f32 "
        "{%0,%1,%2,%3}, {%4,%5,%6,%7}, {%8,%9}, {%0,%1,%2,%3};\n"
        : "+f"(d[0]), "+f"(d[1]), "+f"(d[2]), "+f"(d[3])
        : "r"(a[0]), "r"(a[1]), "r"(a[2]), "r"(a[3]), "r"(b[0]), "r"(b[1]));
}

// ---------------- prep: weight transpose/convert + c/f vectors ----------------
// grid 80: blocks 0-7 -> WdT (d-chunks of 128), 8-15 -> WuT (n-chunks of 128),
// 16-79 -> c[j], f[j] (one block per j)
__global__ void prep_kernel(const float* __restrict__ norm_w,
                            const float* __restrict__ norm_b,
                            const float* __restrict__ w_down,
                            const float* __restrict__ b_down,
                            const float* __restrict__ w_up)
{
    __shared__ float s[8704];   // 34 KB scratch, reused per-branch
    __shared__ float rc[256], rf[256];
    const int b = blockIdx.x, tid = threadIdx.x;

    if (b < 8) {
        const int d0 = b * 128;
        float (*sd)[65] = reinterpret_cast<float(*)[65]>(s);   // 128 x 65
        for (int i = tid; i < 128 * 64 / 4; i += 256) {
            int idx = i * 4; int d = idx >> 6; int j = idx & 63;
            float4 v = *(const float4*)(w_down + (size_t)(d0 + d) * 64 + j);
            sd[d][j] = v.x; sd[d][j + 1] = v.y; sd[d][j + 2] = v.z; sd[d][j + 3] = v.w;
        }
        __syncthreads();
        for (int q = tid; q < 64 * 16; q += 256) {
            int j = q >> 4; int d8 = q & 15;
            __nv_bfloat16 tmp[8];
#pragma unroll
            for (int e = 0; e < 8; e++) {
                int d = d8 * 8 + e;
                tmp[e] = __float2bfloat16(norm_w[d0 + d] * sd[d][j]);
            }
            *(uint4*)(g_WdT + (size_t)j * DIM + d0 + d8 * 8) = *(uint4*)tmp;
        }
    } else if (b < 16) {
        const int n0 = (b - 8) * 128;
        float (*su)[130] = reinterpret_cast<float(*)[130]>(s); // 64 x 130
        for (int i = tid; i < 64 * 128 / 4; i += 256) {
            int idx = i * 4; int k = idx >> 7; int n = idx & 127;
            float4 v = *(const float4*)(w_up + (size_t)k * DIM + n0 + n);
            su[k][n] = v.x; su[k][n + 1] = v.y; su[k][n + 2] = v.z; su[k][n + 3] = v.w;
        }
        __syncthreads();
        for (int q = tid; q < 128 * 8; q += 256) {
            int n = q >> 3; int k8 = q & 7;
            __nv_bfloat16 tmp[8];
#pragma unroll
            for (int e = 0; e < 8; e++)
                tmp[e] = __float2bfloat16(su[k8 * 8 + e][n]);
            *(uint4*)(g_WuT + (size_t)(n0 + n) * BOT + k8 * 8) = *(uint4*)tmp;
        }
    } else {
        const int j = b - 16;  // 0..63
        float c = 0.f, f = 0.f;
        for (int d = tid; d < DIM; d += 256) {
            float w = w_down[(size_t)d * 64 + j];
            c += norm_w[d] * w;
            f += norm_b[d] * w;
        }
        rc[tid] = c; rf[tid] = f;
        __syncthreads();
        for (int st = 128; st > 0; st >>= 1) {
            if (tid < st) { rc[tid] += rc[tid + st]; rf[tid] += rf[tid + st]; }
            __syncthreads();
        }
        if (tid == 0) { g_cf[j] = rc[0]; g_cf[64 + j] = rf[0] + b_down[j]; }
    }
}

// ---------------- main fused kernel ----------------
struct __align__(16) MainSmem {
    union {
        struct {
            __nv_bfloat16 xs[2][MTILE][SPAD];   // x tile staged as bf16
            __nv_bfloat16 wd[2][BOT][SPAD];     // WdT chunk [j][k]
        } a;
        struct {
            __nv_bfloat16 wu[2][NCH][SPAD];     // WuT chunk [n][k]
        } b2;
    } u;                                         // 36864 B
    __nv_bfloat16 gs[MTILE][SPAD];               // gelu(g) tile [r][k]  9216 B
    float mu[MTILE];
    float rstd[MTILE];
    float cf[2 * BOT];
};                                               // total 47104 B < 48 KB

__global__ __launch_bounds__(NTHR, 2)
void adapter_kernel(const float* __restrict__ x,
                    const float* __restrict__ b_up,
                    const float* __restrict__ scale_p,
                    float* __restrict__ out)
{
    __shared__ MainSmem S;
    const int tid  = threadIdx.x;
    const int warp = tid >> 5, lane = tid & 31;
    const int g    = lane >> 2, t4 = lane & 3;     // mma lane decomposition
    const int wm   = warp >> 2, wn = warp & 3;     // 4x4 warp grid
    const int row0 = blockIdx.x * MTILE;

    if (tid < 128) S.cf[tid] = g_cf[tid];

    // loader mapping: row lr (0..63), col-group lt (0..7), 8 floats each
    const int lr = (warp << 2) + (lane >> 3);
    const int lt = lane & 7;
    const float* xrow = x + (size_t)(row0 + lr) * DIM + lt * 8;

    // cp.async mapping for weight chunks: 64 rows x 8 x 16B
    const int wj = tid >> 3, w8 = tid & 7;

    // ---- phase A prologue ----
    float4 ra = *(const float4*)(xrow);
    float4 rb = *(const float4*)(xrow + 4);
    cp16(&S.u.a.wd[0][wj][w8 * 8], g_WdT + (size_t)wj * DIM + w8 * 8);
    cp_commit();

    float s1 = 0.f, s2 = 0.f;
    float acc1[2][4] = {};

    // ---- phase A: stats + bf16 stage + GEMM1 (x @ Wd'), K-chunked ----
#pragma unroll 1
    for (int kc = 0; kc < NKC; kc++) {
        const int cur = kc & 1;
        {
            float v[8] = {ra.x, ra.y, ra.z, ra.w, rb.x, rb.y, rb.z, rb.w};
            uint32_t pk[4];
#pragma unroll
            for (int i = 0; i < 4; i++) {
                float p = v[2 * i], q = v[2 * i + 1];
                s1 += p + q; s2 += p * p + q * q;
                __nv_bfloat162 h2 = __floats2bfloat162_rn(p, q);
                pk[i] = *reinterpret_cast<uint32_t*>(&h2);
            }
            *(uint4*)&S.u.a.xs[cur][lr][lt * 8] = make_uint4(pk[0], pk[1], pk[2], pk[3]);
        }
        if (kc + 1 < NKC) {  // prefetch next x chunk into regs (overlaps mma)
            ra = *(const float4*)(xrow + (kc + 1) * KC);
            rb = *(const float4*)(xrow + (kc + 1) * KC + 4);
        }
        cp_wait0();          // wd[cur] arrived (this thread's copies)
        __syncthreads();     // xs[cur]+wd[cur] visible; prior buffer free
        if (kc + 1 < NKC) {  // prefetch next weight chunk
            cp16(&S.u.a.wd[1 - cur][wj][w8 * 8],
                 g_WdT + (size_t)wj * DIM + (kc + 1) * KC + w8 * 8);
            cp_commit();
        }
#pragma unroll
        for (int ks = 0; ks < 4; ks++) {
            uint32_t afr[4];
            const __nv_bfloat16* xp = &S.u.a.xs[cur][wm * 16 + g][ks * 16 + t4 * 2];
            afr[0] = *(const uint32_t*)xp;
            afr[1] = *(const uint32_t*)(xp + 8 * SPAD);
            afr[2] = *(const uint32_t*)(xp + 8);
            afr[3] = *(const uint32_t*)(xp + 8 * SPAD + 8);
#pragma unroll
            for (int h = 0; h < 2; h++) {
                uint32_t bfr[2];
                const __nv_bfloat16* wp = &S.u.a.wd[cur][wn * 16 + h * 8 + g][ks * 16 + t4 * 2];
                bfr[0] = *(const uint32_t*)wp;
                bfr[1] = *(const uint32_t*)(wp + 8);
                mma_bf16(acc1[h], afr, bfr);
            }
        }
    }

    // ---- LN stats finalize (fp32 exact) ----
#pragma unroll
    for (int off = 4; off; off >>= 1) {
        s1 += __shfl_xor_sync(0xffffffffu, s1, off);
        s2 += __shfl_xor_sync(0xffffffffu, s2, off);
    }
    if (lt == 0) {
        float m   = s1 * (1.0f / 1024.0f);
        float var = s2 * (1.0f / 1024.0f) - m * m;
        S.mu[lr]   = m;
        S.rstd[lr] = rsqrtf(var + 1e-5f);
    }
    __syncthreads();   // all phase-A smem reads complete; stats published

    // prefetch wu chunk 0 (union region now free)
    const int un = tid >> 3;
    cp16(&S.u.b2.wu[0][un][w8 * 8],      g_WuT + (size_t)un * BOT + w8 * 8);
    cp16(&S.u.b2.wu[0][un + 64][w8 * 8], g_WuT + (size_t)(un + 64) * BOT + w8 * 8);
    cp_commit();

    // ---- affine correction + exact GELU -> gs (bf16) ----
    {
        const float mua = S.mu[wm * 16 + g],     rsa = S.rstd[wm * 16 + g];
        const float mub = S.mu[wm * 16 + g + 8], rsb = S.rstd[wm * 16 + g + 8];
#pragma unroll
        for (int h = 0; h < 2; h++) {
            int j0 = wn * 16 + h * 8 + t4 * 2;
            float c0 = S.cf[j0], c1 = S.cf[j0 + 1];
            float f0 = S.cf[64 + j0], f1 = S.cf[64 + j0 + 1];
            float z00 = rsa * (acc1[h][0] - mua * c0) + f0;
            float z01 = rsa * (acc1[h][1] - mua * c1) + f1;
            float z10 = rsb * (acc1[h][2] - mub * c0) + f0;
            float z11 = rsb * (acc1[h][3] - mub * c1) + f1;
            z00 = 0.5f * z00 * (1.0f + erff(z00 * 0.70710678118f));
            z01 = 0.5f * z01 * (1.0f + erff(z01 * 0.70710678118f));
            z10 = 0.5f * z10 * (1.0f + erff(z10 * 0.70710678118f));
            z11 = 0.5f * z11 * (1.0f + erff(z11 * 0.70710678118f));
            __nv_bfloat162 p0 = __floats2bfloat162_rn(z00, z01);
            __nv_bfloat162 p1 = __floats2bfloat162_rn(z10, z11);
            *(uint32_t*)&S.gs[wm * 16 + g][j0]     = *reinterpret_cast<uint32_t*>(&p0);
            *(uint32_t*)&S.gs[wm * 16 + g + 8][j0] = *reinterpret_cast<uint32_t*>(&p1);
        }
    }
    const float scale = *scale_p;

    // ---- phase B: GEMM2 (gelu @ w_up) in N-chunks, fused residual epilogue ----
#pragma unroll 1
    for (int nc = 0; nc < NNC; nc++) {
        const int cur = nc & 1;
        cp_wait0();
        __syncthreads();   // wu[cur] + gs visible; wu[1-cur] readers done
        if (nc + 1 < NNC) {
            cp16(&S.u.b2.wu[1 - cur][un][w8 * 8],
                 g_WuT + (size_t)((nc + 1) * NCH + un) * BOT + w8 * 8);
            cp16(&S.u.b2.wu[1 - cur][un + 64][w8 * 8],
                 g_WuT + (size_t)((nc + 1) * NCH + un + 64) * BOT + w8 * 8);
            cp_commit();
        }
        float acc2[4][4] = {};
#pragma unroll
        for (int ks = 0; ks < 4; ks++) {
            uint32_t afr[4];
            const __nv_bfloat16* gp = &S.gs[wm * 16 + g][ks * 16 + t4 * 2];
            afr[0] = *(const uint32_t*)gp;
            afr[1] = *(const uint32_t*)(gp + 8 * SPAD);
            afr[2] = *(const uint32_t*)(gp + 8);
            afr[3] = *(const uint32_t*)(gp + 8 * SPAD + 8);
#pragma unroll
            for (int sub = 0; sub < 4; sub++) {
                uint32_t bfr[2];
                const __nv_bfloat16* wp = &S.u.b2.wu[cur][wn * 32 + sub * 8 + g][ks * 16 + t4 * 2];
                bfr[0] = *(const uint32_t*)wp;
                bfr[1] = *(const uint32_t*)(wp + 8);
                mma_bf16(acc2[sub], afr, bfr);
            }
        }
        // epilogue: out = x + scale*(h + b_up), x re-read (L2-resident)
        const int rowa = row0 + wm * 16 + g;
#pragma unroll
        for (int sub = 0; sub < 4; sub++) {
            int col = nc * NCH + wn * 32 + sub * 8 + t4 * 2;
            float2 bu = *(const float2*)(b_up + col);
            float2 xa = *(const float2*)(x + (size_t)rowa * DIM + col);
            float2 xb = *(const float2*)(x + (size_t)(rowa + 8) * DIM + col);
            float2 oa, ob;
            oa.x = xa.x + scale * (acc2[sub][0] + bu.x);
            oa.y = xa.y + scale * (acc2[sub][1] + bu.y);
            ob.x = xb.x + scale * (acc2[sub][2] + bu.x);
            ob.y = xb.y + scale * (acc2[sub][3] + bu.y);
            *(float2*)(out + (size_t)rowa * DIM + col)       = oa;
            *(float2*)(out + (size_t)(rowa + 8) * DIM + col) = ob;
        }
    }
}

// ---------------- launch ----------------
extern "C" void kernel_launch(void* const* d_in, const int* in_sizes, int n_in,
                              void* d_out, int out_size)
{
    const float* x      = (const float*)d_in[0];
    const float* norm_w = (const float*)d_in[1];
    const float* norm_b = (const float*)d_in[2];
    const float* w_down = (const float*)d_in[3];
    const float* b_down = (const float*)d_in[4];
    const float* w_up   = (const float*)d_in[5];
    const float* b_up   = (const float*)d_in[6];
    const float* scale  = (const float*)d_in[7];
    float* out = (float*)d_out;

    prep_kernel<<<80, 256>>>(norm_w, norm_b, w_down, b_down, w_up);
    adapter_kernel<<<TOT_ROWS / MTILE, NTHR>>>(x, b_up, scale, out);
}